// round 4
// baseline (speedup 1.0000x reference)
#include <cuda_runtime.h>

// LIF scan: X[B,C,H,W,T=16] fp32 -> spikes same shape.
// mem = mem*0.5 + x_t; s = (mem >= 1); mem = s ? 0 : mem
//
// R3 insight: global side must be perfectly coalesced; transpose via swizzled smem.
// R4 change: the transpose is warp-local (each warp's 4 coalesced LDG.128s cover
// exactly its 32 neurons), so all block-wide __syncthreads are replaced by
// __syncwarp over per-warp smem regions. Warps free-run -> loads stay in flight
// continuously instead of CTA-phased bursts.

#define DECAY  0.5f
#define THRESH 1.0f
#define T_STEPS 16
#define THREADS 256
#define WARPS   (THREADS / 32)
#define F4_PER_WARP 128            // 32 neurons * 4 float4

// Swizzled float4 slot for (warp-local neuron n in 0..31, logical quarter j)
__device__ __forceinline__ int slot(int n, int j) {
    return n * 4 + (j ^ ((n ^ (n >> 2)) & 3));
}

__global__ void __launch_bounds__(THREADS)
lif_kernel(const float4* __restrict__ x4, float4* __restrict__ o4) {
    __shared__ float4 sm[WARPS * F4_PER_WARP];

    const int tid  = threadIdx.x;
    const int lane = tid & 31;
    const int wid  = tid >> 5;
    float4* wsm = sm + wid * F4_PER_WARP;

    // This warp's contiguous global region (in float4 units)
    const size_t base = (size_t)blockIdx.x * (THREADS * 4) + (size_t)wid * F4_PER_WARP;

    // ---- Stage in: 4 coalesced LDG.128 per lane, swizzled STS ----
#pragma unroll
    for (int i = 0; i < 4; i++) {
        float4 v = x4[base + i * 32 + lane];
        int x = i * 32 + lane;
        wsm[slot(x >> 2, x & 3)] = v;
    }
    __syncwarp();

    // ---- Gather own neuron (16 floats), conflict-free LDS.128 ----
    const int n   = lane;
    const int swz = (n ^ (n >> 2)) & 3;
    float4 q0 = wsm[n * 4 + (0 ^ swz)];
    float4 q1 = wsm[n * 4 + (1 ^ swz)];
    float4 q2 = wsm[n * 4 + (2 ^ swz)];
    float4 q3 = wsm[n * 4 + (3 ^ swz)];

    float f[T_STEPS] = { q0.x,q0.y,q0.z,q0.w, q1.x,q1.y,q1.z,q1.w,
                         q2.x,q2.y,q2.z,q2.w, q3.x,q3.y,q3.z,q3.w };

    float mem = 0.0f;
#pragma unroll
    for (int i = 0; i < T_STEPS; i++) {
        mem = fmaf(mem, DECAY, f[i]);
        bool fire = (mem >= THRESH);
        f[i] = fire ? 1.0f : 0.0f;
        mem  = fire ? 0.0f : mem;
    }

    // ---- Write back into own slots (only this thread touches them) ----
    wsm[n * 4 + (0 ^ swz)] = make_float4(f[0],  f[1],  f[2],  f[3]);
    wsm[n * 4 + (1 ^ swz)] = make_float4(f[4],  f[5],  f[6],  f[7]);
    wsm[n * 4 + (2 ^ swz)] = make_float4(f[8],  f[9],  f[10], f[11]);
    wsm[n * 4 + (3 ^ swz)] = make_float4(f[12], f[13], f[14], f[15]);
    __syncwarp();

    // ---- Stage out: swizzled LDS, 4 coalesced STG.128 per lane ----
#pragma unroll
    for (int i = 0; i < 4; i++) {
        int x = i * 32 + lane;
        o4[base + x] = wsm[slot(x >> 2, x & 3)];
    }
}

extern "C" void kernel_launch(void* const* d_in, const int* in_sizes, int n_in,
                              void* d_out, int out_size) {
    const float4* x4 = (const float4*)d_in[0];
    float4* o4 = (float4*)d_out;
    int n_total = in_sizes[0];                   // 67108864 floats
    int n_neurons = n_total / T_STEPS;           // 4194304
    int blocks = n_neurons / THREADS;            // 16384
    lif_kernel<<<blocks, THREADS>>>(x4, o4);
}

// round 5
// speedup vs baseline: 1.0055x; 1.0055x over previous
#include <cuda_runtime.h>

// LIF scan: X[B,C,H,W,T=16] fp32 -> spikes same shape.
// mem = mem*0.5 + x_t; s = (mem >= 1); mem = s ? 0 : mem
//
// Structure (from R3/R4): perfectly coalesced global LDG/STG.128, warp-local
// swizzled smem transpose (bank-conflict-free both phases), warp-only syncs.
// R5: evict-first streaming policy (.cs) on all global traffic — data is
// touch-once; keep L2 from churning dead lines against the incoming stream.

#define DECAY  0.5f
#define THRESH 1.0f
#define T_STEPS 16
#define THREADS 256
#define WARPS   (THREADS / 32)
#define F4_PER_WARP 128            // 32 neurons * 4 float4

__device__ __forceinline__ float4 ldcs4(const float4* p) {
    float4 v;
    asm volatile("ld.global.cs.v4.f32 {%0,%1,%2,%3}, [%4];"
                 : "=f"(v.x), "=f"(v.y), "=f"(v.z), "=f"(v.w) : "l"(p));
    return v;
}
__device__ __forceinline__ void stcs4(float4* p, float4 v) {
    asm volatile("st.global.cs.v4.f32 [%0], {%1,%2,%3,%4};"
                 :: "l"(p), "f"(v.x), "f"(v.y), "f"(v.z), "f"(v.w) : "memory");
}

// Swizzled float4 slot for (warp-local neuron n in 0..31, logical quarter j)
__device__ __forceinline__ int slot(int n, int j) {
    return n * 4 + (j ^ ((n ^ (n >> 2)) & 3));
}

__global__ void __launch_bounds__(THREADS)
lif_kernel(const float4* __restrict__ x4, float4* __restrict__ o4) {
    __shared__ float4 sm[WARPS * F4_PER_WARP];

    const int tid  = threadIdx.x;
    const int lane = tid & 31;
    const int wid  = tid >> 5;
    float4* wsm = sm + wid * F4_PER_WARP;

    const size_t base = (size_t)blockIdx.x * (THREADS * 4) + (size_t)wid * F4_PER_WARP;

    // ---- Stage in: 4 coalesced streaming LDG.128 per lane, swizzled STS ----
#pragma unroll
    for (int i = 0; i < 4; i++) {
        float4 v = ldcs4(x4 + base + i * 32 + lane);
        int x = i * 32 + lane;
        wsm[slot(x >> 2, x & 3)] = v;
    }
    __syncwarp();

    // ---- Gather own neuron (16 floats), conflict-free LDS.128 ----
    const int n   = lane;
    const int swz = (n ^ (n >> 2)) & 3;
    float4 q0 = wsm[n * 4 + (0 ^ swz)];
    float4 q1 = wsm[n * 4 + (1 ^ swz)];
    float4 q2 = wsm[n * 4 + (2 ^ swz)];
    float4 q3 = wsm[n * 4 + (3 ^ swz)];

    float f[T_STEPS] = { q0.x,q0.y,q0.z,q0.w, q1.x,q1.y,q1.z,q1.w,
                         q2.x,q2.y,q2.z,q2.w, q3.x,q3.y,q3.z,q3.w };

    float mem = 0.0f;
#pragma unroll
    for (int i = 0; i < T_STEPS; i++) {
        mem = fmaf(mem, DECAY, f[i]);
        bool fire = (mem >= THRESH);
        f[i] = fire ? 1.0f : 0.0f;
        mem  = fire ? 0.0f : mem;
    }

    // ---- Write back into own slots (only this thread touches them) ----
    wsm[n * 4 + (0 ^ swz)] = make_float4(f[0],  f[1],  f[2],  f[3]);
    wsm[n * 4 + (1 ^ swz)] = make_float4(f[4],  f[5],  f[6],  f[7]);
    wsm[n * 4 + (2 ^ swz)] = make_float4(f[8],  f[9],  f[10], f[11]);
    wsm[n * 4 + (3 ^ swz)] = make_float4(f[12], f[13], f[14], f[15]);
    __syncwarp();

    // ---- Stage out: swizzled LDS, 4 coalesced streaming STG.128 per lane ----
#pragma unroll
    for (int i = 0; i < 4; i++) {
        int x = i * 32 + lane;
        stcs4(o4 + base + x, wsm[slot(x >> 2, x & 3)]);
    }
}

extern "C" void kernel_launch(void* const* d_in, const int* in_sizes, int n_in,
                              void* d_out, int out_size) {
    const float4* x4 = (const float4*)d_in[0];
    float4* o4 = (float4*)d_out;
    int n_total = in_sizes[0];                   // 67108864 floats
    int n_neurons = n_total / T_STEPS;           // 4194304
    int blocks = n_neurons / THREADS;            // 16384
    lif_kernel<<<blocks, THREADS>>>(x4, o4);
}